// round 11
// baseline (speedup 1.0000x reference)
#include <cuda_runtime.h>

#define H 512
#define W 512
#define C 3
#define HW (H * W)
#define CHW (C * H * W)
#define N_IT 30

static constexpr float TAU      = (float)0.01;
static constexpr float LAM2     = (float)0.15;
static constexpr float RHO      = (float)1.99;
static constexpr float SIGMA    = (float)(1.0 / 0.01 / 72.0);
static constexpr float TAU_LAM1 = (float)(0.01 * 0.1);
static constexpr float INV_1PT  = (float)(1.0 / 1.01);

// Tiles: 32 rows x 64 cols. Per channel: 16 x 8 = 128 tiles; 384 total.
static constexpr int NBLK = 384;

// SoA scratch planes (static device arrays — no cudaMalloc anywhere)
__device__ float g_u0[CHW], g_u1[CHW], g_u2p[CHW], g_u3[CHW];
__device__ float g_px[CHW], g_p0[CHW], g_p1[CHW];
__device__ volatile int g_cnt[NBLK];   // per-block phase counters

__device__ __forceinline__ float4 ld4(const float* p) {
    return *reinterpret_cast<const float4*>(p);
}
__device__ __forceinline__ float4 ldcg4(const float* p) {
    return __ldcg(reinterpret_cast<const float4*>(p));
}
__device__ __forceinline__ void st4(float* p, float a, float b, float c, float d) {
    *reinterpret_cast<float4*>(p) = make_float4(a, b, c, d);
}

// ---------------------------------------------------------------------------
// Init: x2 = y, r2 = 0 (in d_out); u planes = 0; counters = 0.
// ---------------------------------------------------------------------------
__global__ __launch_bounds__(256) void k_init(const float* __restrict__ y,
                                              float* __restrict__ x2,
                                              float* __restrict__ r2f) {
    int t = blockIdx.x * blockDim.x + threadIdx.x;
    int idx = t * 4;
    *reinterpret_cast<float4*>(x2 + idx) = ld4(y + idx);
    st4(r2f + 2 * idx,     0.f, 0.f, 0.f, 0.f);
    st4(r2f + 2 * idx + 4, 0.f, 0.f, 0.f, 0.f);
    st4(g_u0 + idx, 0.f, 0.f, 0.f, 0.f);
    st4(g_u1 + idx, 0.f, 0.f, 0.f, 0.f);
    st4(g_u2p + idx, 0.f, 0.f, 0.f, 0.f);
    st4(g_u3 + idx, 0.f, 0.f, 0.f, 0.f);
    if (blockIdx.x == 0) {
        for (int m = threadIdx.x; m < NBLK; m += 256) g_cnt[m] = 0;
    }
}

// ---------------------------------------------------------------------------
// Phase A body (identical math to R8 k_A) for one 4-pixel quad at idx.
// Cross-block taps (±W rows, ±col scalars) via __ldcg (L2, coherent);
// own-center and pointwise state via normal loads.
// ---------------------------------------------------------------------------
__device__ __forceinline__ void phaseA(int idx, float* __restrict__ x2,
                                       float* __restrict__ r2f,
                                       const float* __restrict__ y) {
    int j0 = idx & (W - 1);
    int i  = (idx >> 9) & (H - 1);
    bool up = (i >= 1), down = (i + 1 < H);
    bool rowlast = (j0 + 4 == W), rowfirst = (j0 == 0);

    const float4 Z = make_float4(0, 0, 0, 0);
    float4 u0cv = ld4(g_u0 + idx);
    float4 u0uv = up   ? ldcg4(g_u0 + idx - W) : Z;
    float4 u0dv = down ? ldcg4(g_u0 + idx + W) : Z;
    float4 u1cv = ld4(g_u1 + idx);
    float4 u1uv = up ? ldcg4(g_u1 + idx - W) : Z;
    float  u1r  = rowlast ? 0.f : __ldcg(g_u1 + idx + 4);
    float  u1ur = (up && !rowlast) ? __ldcg(g_u1 + idx - W + 4) : 0.f;
    float4 u2cv = ld4(g_u2p + idx);
    float  u2l  = rowfirst ? 0.f : __ldcg(g_u2p + idx - 1);
    float  u2r  = rowlast  ? 0.f : __ldcg(g_u2p + idx + 4);
    float4 u3cv = ld4(g_u3 + idx);
    float4 u3uv = up ? ldcg4(g_u3 + idx - W) : Z;
    float  u3l  = rowfirst ? 0.f : __ldcg(g_u3 + idx - 1);
    float  u3ul = (up && !rowfirst) ? __ldcg(g_u3 + idx - W - 1) : 0.f;

    float u0c[4] = {u0cv.x, u0cv.y, u0cv.z, u0cv.w};
    float u0u[4] = {u0uv.x, u0uv.y, u0uv.z, u0uv.w};
    float u0d[4] = {u0dv.x, u0dv.y, u0dv.z, u0dv.w};
    float u1c[5] = {u1cv.x, u1cv.y, u1cv.z, u1cv.w, u1r};
    float u1u[5] = {u1uv.x, u1uv.y, u1uv.z, u1uv.w, u1ur};
    float u2w[6] = {u2l, u2cv.x, u2cv.y, u2cv.z, u2cv.w, u2r};
    float u3w[5] = {u3l, u3cv.x, u3cv.y, u3cv.z, u3cv.w};
    float u3uw[5]= {u3ul, u3uv.x, u3uv.y, u3uv.z, u3uv.w};

    float4 xo4 = ld4(x2 + idx);
    float4 y4  = ld4(y + idx);
    float4 rA  = ld4(r2f + 2 * idx);
    float4 rB  = ld4(r2f + 2 * idx + 4);
    float xoa[4] = {xo4.x, xo4.y, xo4.z, xo4.w};
    float ya[4]  = {y4.x, y4.y, y4.z, y4.w};
    float ro0[4] = {rA.x, rA.z, rB.x, rB.z};
    float ro1[4] = {rA.y, rA.w, rB.y, rB.w};

    float pxo[4], p0o[4], p1o[4], xno[4], rn0[4], rn1[4];
#pragma unroll
    for (int k = 0; k < 4; ++k) {
        bool lok = (k > 0) || !rowfirst;
        bool rok = (k < 3) || !rowlast;

        float t0c = TAU * (u0c[k] - (down ? u0d[k] : 0.f)
                           + (lok ? u1c[k] : 0.f) - (rok ? u1c[k + 1] : 0.f));
        float t1c = TAU * (u2w[k + 1] - (rok ? u2w[k + 2] : 0.f)
                           + (up ? u3uw[k + 1] : 0.f) - (down ? u3w[k + 1] : 0.f));
        float t0u = up ? TAU * (u0u[k] - u0c[k]
                                + (lok ? u1u[k] : 0.f) - (rok ? u1u[k + 1] : 0.f))
                       : 0.f;
        float t1l = lok ? TAU * (u2w[k] - u2w[k + 1]
                                 + (up ? u3uw[k] : 0.f) - (down ? u3w[k] : 0.f))
                        : 0.f;

        float dv = t0u - (down ? t0c : 0.f) + t1l - (rok ? t1c : 0.f);
        float x  = (xoa[k] - dv + TAU * ya[k]) * INV_1PT;

        float rr0 = ro0[k] + t0c;
        float rr1 = ro1[k] + t1c;
        float s   = rr0 * rr0 + rr1 * rr1;
        float im  = fminf(TAU_LAM1 * rsqrtf(s), 1.0f);
        float r0  = rr0 - rr0 * im;
        float r1  = rr1 - rr1 * im;

        pxo[k] = 2.0f * x - xoa[k];
        p0o[k] = 2.0f * r0 - ro0[k];
        p1o[k] = 2.0f * r1 - ro1[k];
        xno[k] = xoa[k] + RHO * (x - xoa[k]);
        rn0[k] = ro0[k] + RHO * (r0 - ro0[k]);
        rn1[k] = ro1[k] + RHO * (r1 - ro1[k]);
    }
    st4(g_px + idx, pxo[0], pxo[1], pxo[2], pxo[3]);
    st4(g_p0 + idx, p0o[0], p0o[1], p0o[2], p0o[3]);
    st4(g_p1 + idx, p1o[0], p1o[1], p1o[2], p1o[3]);
    st4(x2 + idx, xno[0], xno[1], xno[2], xno[3]);
    st4(r2f + 2 * idx,     rn0[0], rn1[0], rn0[1], rn1[1]);
    st4(r2f + 2 * idx + 4, rn0[2], rn1[2], rn0[3], rn1[3]);
}

// ---------------------------------------------------------------------------
// Phase B body (identical math to R8 k_B) for one 4-pixel quad at idx.
// ---------------------------------------------------------------------------
__device__ __forceinline__ void phaseB(int idx, float4* __restrict__ u2out,
                                       int last) {
    int j0 = idx & (W - 1);
    int i  = (idx >> 9) & (H - 1);
    bool up = (i >= 1), down = (i + 1 < H);
    bool rowlast = (j0 + 4 == W), rowfirst = (j0 == 0);

    const float4 Z = make_float4(0, 0, 0, 0);
    float4 pxc = ld4(g_px + idx);
    float4 pxu = up   ? ldcg4(g_px + idx - W) : Z;
    float4 pxd = down ? ldcg4(g_px + idx + W) : Z;
    float pxl  = rowfirst ? 0.f : __ldcg(g_px + idx - 1);
    float pxr  = rowlast  ? 0.f : __ldcg(g_px + idx + 4);
    float pxdl = (down && !rowfirst) ? __ldcg(g_px + idx + W - 1) : 0.f;
    float pxdr = (down && !rowlast)  ? __ldcg(g_px + idx + W + 4) : 0.f;

    float4 p0c = ld4(g_p0 + idx);
    float4 p0u = up ? ldcg4(g_p0 + idx - W) : Z;
    float  p0l = rowfirst ? 0.f : __ldcg(g_p0 + idx - 1);
    float4 p1c = ld4(g_p1 + idx);
    float  p1l = rowfirst ? 0.f : __ldcg(g_p1 + idx - 1);
    float4 p1d = down ? ldcg4(g_p1 + idx + W) : Z;

    float pxa[6]  = {pxl, pxc.x, pxc.y, pxc.z, pxc.w, pxr};
    float pxda[6] = {pxdl, pxd.x, pxd.y, pxd.z, pxd.w, pxdr};
    float pxua[4] = {pxu.x, pxu.y, pxu.z, pxu.w};
    float p0w[5]  = {p0l, p0c.x, p0c.y, p0c.z, p0c.w};
    float p0ua[4] = {p0u.x, p0u.y, p0u.z, p0u.w};
    float p1w[5]  = {p1l, p1c.x, p1c.y, p1c.z, p1c.w};
    float p1da[4] = {p1d.x, p1d.y, p1d.z, p1d.w};

    float4 u0c = ld4(g_u0 + idx);
    float4 u1c = ld4(g_u1 + idx);
    float4 u2c = ld4(g_u2p + idx);
    float4 u3c = ld4(g_u3 + idx);
    float uo0[4] = {u0c.x, u0c.y, u0c.z, u0c.w};
    float uo1[4] = {u1c.x, u1c.y, u1c.z, u1c.w};
    float uo2[4] = {u2c.x, u2c.y, u2c.z, u2c.w};
    float uo3[4] = {u3c.x, u3c.y, u3c.z, u3c.w};

    float nu0[4], nu1[4], nu2[4], nu3[4];
#pragma unroll
    for (int k = 0; k < 4; ++k) {
        int kc = k + 1;
        bool lok = (k > 0) || !rowfirst;
        bool rok = (k < 3) || !rowlast;

        float q0c = (down ? (pxda[kc] - pxa[kc]) : 0.f) - p0w[k + 1];
        float q0u = up  ? ((pxa[kc] - pxua[k]) - p0ua[k]) : 0.f;
        float q0l = lok ? ((down ? (pxda[kc - 1] - pxa[kc - 1]) : 0.f) - p0w[k]) : 0.f;
        float q1c = (rok ? (pxa[kc + 1] - pxa[kc]) : 0.f) - p1w[k + 1];
        float q1l = lok ? ((pxa[kc] - pxa[kc - 1]) - p1w[k]) : 0.f;
        float q1d = down ? ((rok ? (pxda[kc + 1] - pxda[kc]) : 0.f) - p1da[k]) : 0.f;

        float e0 = q0c - q0u;
        float e1 = lok ? (q0c - q0l) : 0.f;
        float e2 = q1c - q1l;
        float e3 = down ? (q1d - q1c) : 0.f;

        float un0 = uo0[k] + SIGMA * e0;
        float un1 = uo1[k] + SIGMA * e1;
        float un2 = uo2[k] + SIGMA * e2;
        float un3 = uo3[k] + SIGMA * e3;

        float s  = un0 * un0 + un1 * un1 + un2 * un2 + un3 * un3;
        float im = fminf(LAM2 * rsqrtf(s), 1.0f);

        nu0[k] = uo0[k] + RHO * (un0 * im - uo0[k]);
        nu1[k] = uo1[k] + RHO * (un1 * im - uo1[k]);
        nu2[k] = uo2[k] + RHO * (un2 * im - uo2[k]);
        nu3[k] = uo3[k] + RHO * (un3 * im - uo3[k]);
    }

    if (last) {
#pragma unroll
        for (int k = 0; k < 4; ++k)
            u2out[idx + k] = make_float4(nu0[k], nu1[k], nu2[k], nu3[k]);
    } else {
        st4(g_u0 + idx, nu0[0], nu0[1], nu0[2], nu0[3]);
        st4(g_u1 + idx, nu1[0], nu1[1], nu1[2], nu1[3]);
        st4(g_u2p + idx, nu2[0], nu2[1], nu2[2], nu2[3]);
        st4(g_u3 + idx, nu3[0], nu3[1], nu3[2], nu3[3]);
    }
}

// ---------------------------------------------------------------------------
// Persistent solver: 384 co-resident blocks (guaranteed by launch_bounds
// min-blocks 3 -> capacity >= 444), neighbor-only release/acquire sync.
// Counter protocol: after A of iter it -> 2*it+1; after B -> 2*it+2.
// Before A of iter it: neighbors >= 2*it (their B of it-1 done: covers both
// RAW on u halos and WAR on our px overwrite). Before B: neighbors >= 2*it+1.
// ---------------------------------------------------------------------------
__global__ __launch_bounds__(256, 3) void k_solve(float* __restrict__ x2,
                                                  float* __restrict__ r2f,
                                                  const float* __restrict__ y,
                                                  float4* __restrict__ u2o) {
    const int tid = threadIdx.x;
    const int bid = blockIdx.x;
    const int c   = bid >> 7;             // 128 tiles per channel
    const int rem = bid & 127;
    const int bi  = rem >> 3;             // 0..15 (32-row tiles)
    const int bj  = rem & 7;              // 0..7  (64-col tiles)
    const int gi0 = bi * 32;
    const int gj0 = bj * 64;
    const int idxA = c * HW + (gi0 + (tid >> 4)) * W + gj0 + (tid & 15) * 4;
    const int idxB = idxA + 16 * W;       // second quad, +16 rows

    // 8-neighborhood (same channel)
    int nb[8]; int nnb = 0;
#pragma unroll
    for (int di = -1; di <= 1; ++di)
#pragma unroll
        for (int dj = -1; dj <= 1; ++dj) {
            if (di == 0 && dj == 0) continue;
            int ni = bi + di, njj = bj + dj;
            if ((unsigned)ni < 16u && (unsigned)njj < 8u)
                nb[nnb++] = (c << 7) + (ni << 3) + njj;
        }
    int myNb = (tid < nnb) ? nb[tid] : -1;

    for (int it = 0; it < N_IT; ++it) {
        if (it > 0) {                      // wait: neighbors finished B of it-1
            if (myNb >= 0) {
                int tgt = 2 * it;
                while (g_cnt[myNb] < tgt) __nanosleep(40);
            }
            __syncthreads();
        }

        phaseA(idxA, x2, r2f, y);
        phaseA(idxB, x2, r2f, y);

        __threadfence();
        __syncthreads();
        if (tid == 0) g_cnt[bid] = 2 * it + 1;

        if (myNb >= 0) {                   // wait: neighbors finished A of it
            int tgt = 2 * it + 1;
            while (g_cnt[myNb] < tgt) __nanosleep(40);
        }
        __syncthreads();

        int last = (it == N_IT - 1) ? 1 : 0;
        phaseB(idxA, u2o, last);
        phaseB(idxB, u2o, last);

        __threadfence();
        __syncthreads();
        if (tid == 0) g_cnt[bid] = 2 * it + 2;
    }
}

// ---------------------------------------------------------------------------
// Host: init + ONE persistent kernel. n_it_max fixed to 30 by setup_inputs().
// ---------------------------------------------------------------------------
extern "C" void kernel_launch(void* const* d_in, const int* in_sizes, int n_in,
                              void* d_out, int out_size) {
    const float* y = (const float*)d_in[0];
    float*  out = (float*)d_out;
    float*  x2  = out;
    float*  r2f = out + CHW;
    float4* u2o = (float4*)(out + 3 * CHW);

    k_init<<<CHW / 4 / 256, 256>>>(y, x2, r2f);
    k_solve<<<NBLK, 256>>>(x2, r2f, y, u2o);
}

// round 12
// speedup vs baseline: 2.6038x; 2.6038x over previous
#include <cuda_runtime.h>

#define H 512
#define W 512
#define C 3
#define HW (H * W)
#define CHW (C * H * W)
#define N_IT 30

static constexpr float TAU      = (float)0.01;
static constexpr float LAM2     = (float)0.15;
static constexpr float RHO      = (float)1.99;
static constexpr float SIGMA    = (float)(1.0 / 0.01 / 72.0);
static constexpr float TAU_LAM1 = (float)(0.01 * 0.1);
static constexpr float INV_1PT  = (float)(1.0 / 1.01);

// SoA scratch planes (static device arrays — no cudaMalloc anywhere)
__device__ float g_u0[CHW], g_u1[CHW], g_u2p[CHW], g_u3[CHW];  // u2 state (SoA)
__device__ float g_px[CHW], g_p0[CHW], g_p1[CHW];               // px, pr planes

__device__ __forceinline__ float4 ld4(const float* p) {
    return *reinterpret_cast<const float4*>(p);
}
__device__ __forceinline__ void st4(float* p, float a, float b, float c, float d) {
    *reinterpret_cast<float4*>(p) = make_float4(a, b, c, d);
}

// 2D tile mapping: block = 16 rows x 64 cols; thread (ti,tj) -> 4 pixels.
__device__ __forceinline__ int tile_idx() {
    int tid = threadIdx.x;
    int bid = blockIdx.x;
    int c   = bid >> 8;
    int rem = bid & 255;
    int bi  = rem >> 3;
    int bj  = rem & 7;
    int gi  = bi * 16 + (tid >> 4);
    int gj  = bj * 64 + (tid & 15) * 4;
    return c * HW + gi * W + gj;
}

// ---------------------------------------------------------------------------
// Setup = init + (algebraically trivial) iteration-0 phase A:
//   x2 = y, r2 = 0, u = 0, px = y, p0 = p1 = 0.
// (With u=0: tmp=0 -> x=y, r=0, px=2y-y=y, over-relaxed x2=y, r2=0.)
// ---------------------------------------------------------------------------
__global__ __launch_bounds__(256) void k_setup(const float* __restrict__ y,
                                               float* __restrict__ x2,
                                               float* __restrict__ r2f) {
    int t = blockIdx.x * blockDim.x + threadIdx.x;
    int idx = t * 4;
    float4 yv = ld4(y + idx);
    *reinterpret_cast<float4*>(x2 + idx)   = yv;
    *reinterpret_cast<float4*>(g_px + idx) = yv;
    st4(r2f + 2 * idx,     0.f, 0.f, 0.f, 0.f);
    st4(r2f + 2 * idx + 4, 0.f, 0.f, 0.f, 0.f);
    st4(g_p0 + idx, 0.f, 0.f, 0.f, 0.f);
    st4(g_p1 + idx, 0.f, 0.f, 0.f, 0.f);
    st4(g_u0 + idx, 0.f, 0.f, 0.f, 0.f);
    st4(g_u1 + idx, 0.f, 0.f, 0.f, 0.f);
    st4(g_u2p + idx, 0.f, 0.f, 0.f, 0.f);
    st4(g_u3 + idx, 0.f, 0.f, 0.f, 0.f);
}

// ---------------------------------------------------------------------------
// Phase A (fused tmp + xr). x2/r2/y loads are hoisted above the grid sync:
// they depend on A of the previous iteration (2 kernels back — complete under
// PDL serialization); only the u loads depend on the immediately preceding B.
// ---------------------------------------------------------------------------
__global__ __launch_bounds__(256) void k_A(float* __restrict__ x2,
                                           float* __restrict__ r2f,
                                           const float* __restrict__ y) {
    int idx = tile_idx();
    int j0 = idx & (W - 1);
    int i  = (idx >> 9) & (H - 1);
    bool up = (i >= 1), down = (i + 1 < H);
    bool rowlast = (j0 + 4 == W), rowfirst = (j0 == 0);

    float4 xo4 = ld4(x2 + idx);
    float4 y4  = ld4(y + idx);
    float4 rA  = ld4(r2f + 2 * idx);
    float4 rB  = ld4(r2f + 2 * idx + 4);

#if __CUDA_ARCH__ >= 900
    cudaGridDependencySynchronize();
#endif

    const float4 Z = make_float4(0, 0, 0, 0);
    float4 u0cv = ld4(g_u0 + idx);
    float4 u0uv = up   ? ld4(g_u0 + idx - W) : Z;
    float4 u0dv = down ? ld4(g_u0 + idx + W) : Z;
    float4 u1cv = ld4(g_u1 + idx);
    float4 u1uv = up ? ld4(g_u1 + idx - W) : Z;
    float  u1r  = rowlast ? 0.f : g_u1[idx + 4];
    float  u1ur = (up && !rowlast) ? g_u1[idx - W + 4] : 0.f;
    float4 u2cv = ld4(g_u2p + idx);
    float  u2l  = rowfirst ? 0.f : g_u2p[idx - 1];
    float  u2r  = rowlast  ? 0.f : g_u2p[idx + 4];
    float4 u3cv = ld4(g_u3 + idx);
    float4 u3uv = up ? ld4(g_u3 + idx - W) : Z;
    float  u3l  = rowfirst ? 0.f : g_u3[idx - 1];
    float  u3ul = (up && !rowfirst) ? g_u3[idx - W - 1] : 0.f;

    float u0c[4] = {u0cv.x, u0cv.y, u0cv.z, u0cv.w};
    float u0u[4] = {u0uv.x, u0uv.y, u0uv.z, u0uv.w};
    float u0d[4] = {u0dv.x, u0dv.y, u0dv.z, u0dv.w};
    float u1c[5] = {u1cv.x, u1cv.y, u1cv.z, u1cv.w, u1r};
    float u1u[5] = {u1uv.x, u1uv.y, u1uv.z, u1uv.w, u1ur};
    float u2w[6] = {u2l, u2cv.x, u2cv.y, u2cv.z, u2cv.w, u2r};
    float u3w[5] = {u3l, u3cv.x, u3cv.y, u3cv.z, u3cv.w};
    float u3uw[5]= {u3ul, u3uv.x, u3uv.y, u3uv.z, u3uv.w};

    float xoa[4] = {xo4.x, xo4.y, xo4.z, xo4.w};
    float ya[4]  = {y4.x, y4.y, y4.z, y4.w};
    float ro0[4] = {rA.x, rA.z, rB.x, rB.z};
    float ro1[4] = {rA.y, rA.w, rB.y, rB.w};

    float pxo[4], p0o[4], p1o[4], xno[4], rn0[4], rn1[4];
#pragma unroll
    for (int k = 0; k < 4; ++k) {
        bool lok = (k > 0) || !rowfirst;          // j >= 1
        bool rok = (k < 3) || !rowlast;           // j < W-1

        float t0c = TAU * (u0c[k] - (down ? u0d[k] : 0.f)
                           + (lok ? u1c[k] : 0.f) - (rok ? u1c[k + 1] : 0.f));
        float t1c = TAU * (u2w[k + 1] - (rok ? u2w[k + 2] : 0.f)
                           + (up ? u3uw[k + 1] : 0.f) - (down ? u3w[k + 1] : 0.f));
        float t0u = up ? TAU * (u0u[k] - u0c[k]
                                + (lok ? u1u[k] : 0.f) - (rok ? u1u[k + 1] : 0.f))
                       : 0.f;
        float t1l = lok ? TAU * (u2w[k] - u2w[k + 1]
                                 + (up ? u3uw[k] : 0.f) - (down ? u3w[k] : 0.f))
                        : 0.f;

        float dv = t0u - (down ? t0c : 0.f) + t1l - (rok ? t1c : 0.f);
        float x  = (xoa[k] - dv + TAU * ya[k]) * INV_1PT;

        float rr0 = ro0[k] + t0c;
        float rr1 = ro1[k] + t1c;
        float s   = rr0 * rr0 + rr1 * rr1;
        float im  = fminf(TAU_LAM1 * rsqrtf(s), 1.0f);
        float r0  = rr0 - rr0 * im;
        float r1  = rr1 - rr1 * im;

        pxo[k] = 2.0f * x - xoa[k];
        p0o[k] = 2.0f * r0 - ro0[k];
        p1o[k] = 2.0f * r1 - ro1[k];
        xno[k] = xoa[k] + RHO * (x - xoa[k]);
        rn0[k] = ro0[k] + RHO * (r0 - ro0[k]);
        rn1[k] = ro1[k] + RHO * (r1 - ro1[k]);
    }
    st4(g_px + idx, pxo[0], pxo[1], pxo[2], pxo[3]);
    st4(g_p0 + idx, p0o[0], p0o[1], p0o[2], p0o[3]);
    st4(g_p1 + idx, p1o[0], p1o[1], p1o[2], p1o[3]);
    st4(x2 + idx, xno[0], xno[1], xno[2], xno[3]);
    st4(r2f + 2 * idx,     rn0[0], rn1[0], rn0[1], rn1[1]);
    st4(r2f + 2 * idx + 4, rn0[2], rn1[2], rn0[3], rn1[3]);
}

// ---------------------------------------------------------------------------
// Phase B. u loads (dep: B two kernels back) hoisted above the grid sync;
// px/p0/p1 loads (dep: immediately preceding A) after.
// ---------------------------------------------------------------------------
__global__ __launch_bounds__(256) void k_B(float4* __restrict__ u2out, int last) {
    int idx = tile_idx();
    int j0 = idx & (W - 1);
    int i  = (idx >> 9) & (H - 1);
    bool up = (i >= 1), down = (i + 1 < H);
    bool rowlast = (j0 + 4 == W), rowfirst = (j0 == 0);

    float4 u0c = ld4(g_u0 + idx);
    float4 u1c = ld4(g_u1 + idx);
    float4 u2c = ld4(g_u2p + idx);
    float4 u3c = ld4(g_u3 + idx);

#if __CUDA_ARCH__ >= 900
    cudaGridDependencySynchronize();
#endif

    float4 pxc = ld4(g_px + idx);
    float4 pxu = up   ? ld4(g_px + idx - W) : make_float4(0, 0, 0, 0);
    float4 pxd = down ? ld4(g_px + idx + W) : make_float4(0, 0, 0, 0);
    float pxl  = rowfirst ? 0.f : g_px[idx - 1];
    float pxr  = rowlast  ? 0.f : g_px[idx + 4];
    float pxdl = (down && !rowfirst) ? g_px[idx + W - 1] : 0.f;
    float pxdr = (down && !rowlast)  ? g_px[idx + W + 4] : 0.f;

    float4 p0c = ld4(g_p0 + idx);
    float4 p0u = up ? ld4(g_p0 + idx - W) : make_float4(0, 0, 0, 0);
    float  p0l = rowfirst ? 0.f : g_p0[idx - 1];
    float4 p1c = ld4(g_p1 + idx);
    float  p1l = rowfirst ? 0.f : g_p1[idx - 1];
    float4 p1d = down ? ld4(g_p1 + idx + W) : make_float4(0, 0, 0, 0);

    float pxa[6]  = {pxl, pxc.x, pxc.y, pxc.z, pxc.w, pxr};
    float pxda[6] = {pxdl, pxd.x, pxd.y, pxd.z, pxd.w, pxdr};
    float pxua[4] = {pxu.x, pxu.y, pxu.z, pxu.w};
    float p0w[5]  = {p0l, p0c.x, p0c.y, p0c.z, p0c.w};
    float p0ua[4] = {p0u.x, p0u.y, p0u.z, p0u.w};
    float p1w[5]  = {p1l, p1c.x, p1c.y, p1c.z, p1c.w};
    float p1da[4] = {p1d.x, p1d.y, p1d.z, p1d.w};

    float uo0[4] = {u0c.x, u0c.y, u0c.z, u0c.w};
    float uo1[4] = {u1c.x, u1c.y, u1c.z, u1c.w};
    float uo2[4] = {u2c.x, u2c.y, u2c.z, u2c.w};
    float uo3[4] = {u3c.x, u3c.y, u3c.z, u3c.w};

    float nu0[4], nu1[4], nu2[4], nu3[4];
#pragma unroll
    for (int k = 0; k < 4; ++k) {
        int kc = k + 1;
        bool lok = (k > 0) || !rowfirst;
        bool rok = (k < 3) || !rowlast;

        float q0c = (down ? (pxda[kc] - pxa[kc]) : 0.f) - p0w[k + 1];
        float q0u = up  ? ((pxa[kc] - pxua[k]) - p0ua[k]) : 0.f;
        float q0l = lok ? ((down ? (pxda[kc - 1] - pxa[kc - 1]) : 0.f) - p0w[k]) : 0.f;
        float q1c = (rok ? (pxa[kc + 1] - pxa[kc]) : 0.f) - p1w[k + 1];
        float q1l = lok ? ((pxa[kc] - pxa[kc - 1]) - p1w[k]) : 0.f;
        float q1d = down ? ((rok ? (pxda[kc + 1] - pxda[kc]) : 0.f) - p1da[k]) : 0.f;

        float e0 = q0c - q0u;
        float e1 = lok ? (q0c - q0l) : 0.f;
        float e2 = q1c - q1l;
        float e3 = down ? (q1d - q1c) : 0.f;

        float un0 = uo0[k] + SIGMA * e0;
        float un1 = uo1[k] + SIGMA * e1;
        float un2 = uo2[k] + SIGMA * e2;
        float un3 = uo3[k] + SIGMA * e3;

        float s  = un0 * un0 + un1 * un1 + un2 * un2 + un3 * un3;
        float im = fminf(LAM2 * rsqrtf(s), 1.0f);

        nu0[k] = uo0[k] + RHO * (un0 * im - uo0[k]);
        nu1[k] = uo1[k] + RHO * (un1 * im - uo1[k]);
        nu2[k] = uo2[k] + RHO * (un2 * im - uo2[k]);
        nu3[k] = uo3[k] + RHO * (un3 * im - uo3[k]);
    }

    if (last) {
#pragma unroll
        for (int k = 0; k < 4; ++k)
            u2out[idx + k] = make_float4(nu0[k], nu1[k], nu2[k], nu3[k]);
    } else {
        st4(g_u0 + idx, nu0[0], nu0[1], nu0[2], nu0[3]);
        st4(g_u1 + idx, nu1[0], nu1[1], nu1[2], nu1[3]);
        st4(g_u2p + idx, nu2[0], nu2[1], nu2[2], nu2[3]);
        st4(g_u3 + idx, nu3[0], nu3[1], nu3[2], nu3[3]);
    }
}

// ---------------------------------------------------------------------------
// PDL launches.
// ---------------------------------------------------------------------------
template <typename... Args>
static inline void launch_pdl(void (*kern)(Args...), int blocks, int threads,
                              Args... args) {
    cudaLaunchConfig_t cfg = {};
    cfg.gridDim  = dim3(blocks);
    cfg.blockDim = dim3(threads);
    cfg.stream   = 0;
    cudaLaunchAttribute attr[1];
    attr[0].id = cudaLaunchAttributeProgrammaticStreamSerialization;
    attr[0].val.programmaticStreamSerializationAllowed = 1;
    cfg.attrs = attr;
    cfg.numAttrs = 1;
    cudaLaunchKernelEx(&cfg, kern, args...);
}

extern "C" void kernel_launch(void* const* d_in, const int* in_sizes, int n_in,
                              void* d_out, int out_size) {
    const float* y = (const float*)d_in[0];
    float*  out = (float*)d_out;
    float*  x2  = out;
    float*  r2f = out + CHW;
    float4* u2o = (float4*)(out + 3 * CHW);

    const int threads = 256;
    const int blocks  = 768;   // 32 i-tiles x 8 j-tiles x 3 channels

    // setup fuses init + trivial A_0
    k_setup<<<CHW / 4 / threads, threads>>>(y, x2, r2f);
    launch_pdl(k_B, blocks, threads, u2o, 0);          // B_0
    for (int it = 1; it < N_IT; ++it) {
        launch_pdl(k_A, blocks, threads, x2, r2f, (const float*)y);
        launch_pdl(k_B, blocks, threads, u2o, it == N_IT - 1 ? 1 : 0);
    }
}

// round 13
// speedup vs baseline: 2.7858x; 1.0699x over previous
#include <cuda_runtime.h>

#define H 512
#define W 512
#define C 3
#define HW (H * W)
#define CHW (C * H * W)
#define N_IT 30

static constexpr float TAU      = (float)0.01;
static constexpr float LAM2     = (float)0.15;
static constexpr float RHO      = (float)1.99;
static constexpr float SIGMA    = (float)(1.0 / 0.01 / 72.0);
static constexpr float TAU_LAM1 = (float)(0.01 * 0.1);
static constexpr float INV_1PT  = (float)(1.0 / 1.01);

// SoA scratch planes (static device arrays — no cudaMalloc anywhere)
__device__ float g_u0[CHW], g_u1[CHW], g_u2p[CHW], g_u3[CHW];  // u2 state (SoA)
__device__ float g_px[CHW], g_p0[CHW], g_p1[CHW];               // px, pr planes

__device__ __forceinline__ float4 ld4(const float* p) {
    return *reinterpret_cast<const float4*>(p);
}
__device__ __forceinline__ void st4(float* p, float a, float b, float c, float d) {
    *reinterpret_cast<float4*>(p) = make_float4(a, b, c, d);
}

// Tile mapping: block = 32 rows x 64 cols; thread -> 2 row-stacked quads.
// Per channel: 16 x 8 = 128 tiles; grid = 384 blocks.
__device__ __forceinline__ int tile_idx2() {
    int tid = threadIdx.x;
    int bid = blockIdx.x;
    int c   = bid >> 7;
    int rem = bid & 127;
    int bi  = rem >> 3;          // 0..15
    int bj  = rem & 7;           // 0..7
    int gi  = bi * 32 + (tid >> 4) * 2;
    int gj  = bj * 64 + (tid & 15) * 4;
    return c * HW + gi * W + gj;
}

// ---------------------------------------------------------------------------
// Setup = init + (algebraically trivial) iteration-0 phase A:
//   x2 = y, r2 = 0, u = 0, px = y, p0 = p1 = 0.
// ---------------------------------------------------------------------------
__global__ __launch_bounds__(256) void k_setup(const float* __restrict__ y,
                                               float* __restrict__ x2,
                                               float* __restrict__ r2f) {
    int t = blockIdx.x * blockDim.x + threadIdx.x;
    int idx = t * 4;
    float4 yv = ld4(y + idx);
    *reinterpret_cast<float4*>(x2 + idx)   = yv;
    *reinterpret_cast<float4*>(g_px + idx) = yv;
    st4(r2f + 2 * idx,     0.f, 0.f, 0.f, 0.f);
    st4(r2f + 2 * idx + 4, 0.f, 0.f, 0.f, 0.f);
    st4(g_p0 + idx, 0.f, 0.f, 0.f, 0.f);
    st4(g_p1 + idx, 0.f, 0.f, 0.f, 0.f);
    st4(g_u0 + idx, 0.f, 0.f, 0.f, 0.f);
    st4(g_u1 + idx, 0.f, 0.f, 0.f, 0.f);
    st4(g_u2p + idx, 0.f, 0.f, 0.f, 0.f);
    st4(g_u3 + idx, 0.f, 0.f, 0.f, 0.f);
}

// ---------------------------------------------------------------------------
// Phase A body (identical math to R8 k_A) for one 4-pixel quad at idx.
// ---------------------------------------------------------------------------
__device__ __forceinline__ void phaseA(int idx, float* __restrict__ x2,
                                       float* __restrict__ r2f,
                                       const float* __restrict__ y) {
    int j0 = idx & (W - 1);
    int i  = (idx >> 9) & (H - 1);
    bool up = (i >= 1), down = (i + 1 < H);
    bool rowlast = (j0 + 4 == W), rowfirst = (j0 == 0);

    const float4 Z = make_float4(0, 0, 0, 0);
    float4 u0cv = ld4(g_u0 + idx);
    float4 u0uv = up   ? ld4(g_u0 + idx - W) : Z;
    float4 u0dv = down ? ld4(g_u0 + idx + W) : Z;
    float4 u1cv = ld4(g_u1 + idx);
    float4 u1uv = up ? ld4(g_u1 + idx - W) : Z;
    float  u1r  = rowlast ? 0.f : g_u1[idx + 4];
    float  u1ur = (up && !rowlast) ? g_u1[idx - W + 4] : 0.f;
    float4 u2cv = ld4(g_u2p + idx);
    float  u2l  = rowfirst ? 0.f : g_u2p[idx - 1];
    float  u2r  = rowlast  ? 0.f : g_u2p[idx + 4];
    float4 u3cv = ld4(g_u3 + idx);
    float4 u3uv = up ? ld4(g_u3 + idx - W) : Z;
    float  u3l  = rowfirst ? 0.f : g_u3[idx - 1];
    float  u3ul = (up && !rowfirst) ? g_u3[idx - W - 1] : 0.f;

    float u0c[4] = {u0cv.x, u0cv.y, u0cv.z, u0cv.w};
    float u0u[4] = {u0uv.x, u0uv.y, u0uv.z, u0uv.w};
    float u0d[4] = {u0dv.x, u0dv.y, u0dv.z, u0dv.w};
    float u1c[5] = {u1cv.x, u1cv.y, u1cv.z, u1cv.w, u1r};
    float u1u[5] = {u1uv.x, u1uv.y, u1uv.z, u1uv.w, u1ur};
    float u2w[6] = {u2l, u2cv.x, u2cv.y, u2cv.z, u2cv.w, u2r};
    float u3w[5] = {u3l, u3cv.x, u3cv.y, u3cv.z, u3cv.w};
    float u3uw[5]= {u3ul, u3uv.x, u3uv.y, u3uv.z, u3uv.w};

    float4 xo4 = ld4(x2 + idx);
    float4 y4  = ld4(y + idx);
    float4 rA  = ld4(r2f + 2 * idx);
    float4 rB  = ld4(r2f + 2 * idx + 4);
    float xoa[4] = {xo4.x, xo4.y, xo4.z, xo4.w};
    float ya[4]  = {y4.x, y4.y, y4.z, y4.w};
    float ro0[4] = {rA.x, rA.z, rB.x, rB.z};
    float ro1[4] = {rA.y, rA.w, rB.y, rB.w};

    float pxo[4], p0o[4], p1o[4], xno[4], rn0[4], rn1[4];
#pragma unroll
    for (int k = 0; k < 4; ++k) {
        bool lok = (k > 0) || !rowfirst;          // j >= 1
        bool rok = (k < 3) || !rowlast;           // j < W-1

        float t0c = TAU * (u0c[k] - (down ? u0d[k] : 0.f)
                           + (lok ? u1c[k] : 0.f) - (rok ? u1c[k + 1] : 0.f));
        float t1c = TAU * (u2w[k + 1] - (rok ? u2w[k + 2] : 0.f)
                           + (up ? u3uw[k + 1] : 0.f) - (down ? u3w[k + 1] : 0.f));
        float t0u = up ? TAU * (u0u[k] - u0c[k]
                                + (lok ? u1u[k] : 0.f) - (rok ? u1u[k + 1] : 0.f))
                       : 0.f;
        float t1l = lok ? TAU * (u2w[k] - u2w[k + 1]
                                 + (up ? u3uw[k] : 0.f) - (down ? u3w[k] : 0.f))
                        : 0.f;

        float dv = t0u - (down ? t0c : 0.f) + t1l - (rok ? t1c : 0.f);
        float x  = (xoa[k] - dv + TAU * ya[k]) * INV_1PT;

        float rr0 = ro0[k] + t0c;
        float rr1 = ro1[k] + t1c;
        float s   = rr0 * rr0 + rr1 * rr1;
        float im  = fminf(TAU_LAM1 * rsqrtf(s), 1.0f);
        float r0  = rr0 - rr0 * im;
        float r1  = rr1 - rr1 * im;

        pxo[k] = 2.0f * x - xoa[k];
        p0o[k] = 2.0f * r0 - ro0[k];
        p1o[k] = 2.0f * r1 - ro1[k];
        xno[k] = xoa[k] + RHO * (x - xoa[k]);
        rn0[k] = ro0[k] + RHO * (r0 - ro0[k]);
        rn1[k] = ro1[k] + RHO * (r1 - ro1[k]);
    }
    st4(g_px + idx, pxo[0], pxo[1], pxo[2], pxo[3]);
    st4(g_p0 + idx, p0o[0], p0o[1], p0o[2], p0o[3]);
    st4(g_p1 + idx, p1o[0], p1o[1], p1o[2], p1o[3]);
    st4(x2 + idx, xno[0], xno[1], xno[2], xno[3]);
    st4(r2f + 2 * idx,     rn0[0], rn1[0], rn0[1], rn1[1]);
    st4(r2f + 2 * idx + 4, rn0[2], rn1[2], rn0[3], rn1[3]);
}

// ---------------------------------------------------------------------------
// Phase B body (identical math to R8 k_B) for one 4-pixel quad at idx.
// ---------------------------------------------------------------------------
__device__ __forceinline__ void phaseB(int idx, float4* __restrict__ u2out,
                                       int last) {
    int j0 = idx & (W - 1);
    int i  = (idx >> 9) & (H - 1);
    bool up = (i >= 1), down = (i + 1 < H);
    bool rowlast = (j0 + 4 == W), rowfirst = (j0 == 0);

    const float4 Z = make_float4(0, 0, 0, 0);
    float4 pxc = ld4(g_px + idx);
    float4 pxu = up   ? ld4(g_px + idx - W) : Z;
    float4 pxd = down ? ld4(g_px + idx + W) : Z;
    float pxl  = rowfirst ? 0.f : g_px[idx - 1];
    float pxr  = rowlast  ? 0.f : g_px[idx + 4];
    float pxdl = (down && !rowfirst) ? g_px[idx + W - 1] : 0.f;
    float pxdr = (down && !rowlast)  ? g_px[idx + W + 4] : 0.f;

    float4 p0c = ld4(g_p0 + idx);
    float4 p0u = up ? ld4(g_p0 + idx - W) : Z;
    float  p0l = rowfirst ? 0.f : g_p0[idx - 1];
    float4 p1c = ld4(g_p1 + idx);
    float  p1l = rowfirst ? 0.f : g_p1[idx - 1];
    float4 p1d = down ? ld4(g_p1 + idx + W) : Z;

    float pxa[6]  = {pxl, pxc.x, pxc.y, pxc.z, pxc.w, pxr};
    float pxda[6] = {pxdl, pxd.x, pxd.y, pxd.z, pxd.w, pxdr};
    float pxua[4] = {pxu.x, pxu.y, pxu.z, pxu.w};
    float p0w[5]  = {p0l, p0c.x, p0c.y, p0c.z, p0c.w};
    float p0ua[4] = {p0u.x, p0u.y, p0u.z, p0u.w};
    float p1w[5]  = {p1l, p1c.x, p1c.y, p1c.z, p1c.w};
    float p1da[4] = {p1d.x, p1d.y, p1d.z, p1d.w};

    float4 u0c = ld4(g_u0 + idx);
    float4 u1c = ld4(g_u1 + idx);
    float4 u2c = ld4(g_u2p + idx);
    float4 u3c = ld4(g_u3 + idx);
    float uo0[4] = {u0c.x, u0c.y, u0c.z, u0c.w};
    float uo1[4] = {u1c.x, u1c.y, u1c.z, u1c.w};
    float uo2[4] = {u2c.x, u2c.y, u2c.z, u2c.w};
    float uo3[4] = {u3c.x, u3c.y, u3c.z, u3c.w};

    float nu0[4], nu1[4], nu2[4], nu3[4];
#pragma unroll
    for (int k = 0; k < 4; ++k) {
        int kc = k + 1;
        bool lok = (k > 0) || !rowfirst;
        bool rok = (k < 3) || !rowlast;

        float q0c = (down ? (pxda[kc] - pxa[kc]) : 0.f) - p0w[k + 1];
        float q0u = up  ? ((pxa[kc] - pxua[k]) - p0ua[k]) : 0.f;
        float q0l = lok ? ((down ? (pxda[kc - 1] - pxa[kc - 1]) : 0.f) - p0w[k]) : 0.f;
        float q1c = (rok ? (pxa[kc + 1] - pxa[kc]) : 0.f) - p1w[k + 1];
        float q1l = lok ? ((pxa[kc] - pxa[kc - 1]) - p1w[k]) : 0.f;
        float q1d = down ? ((rok ? (pxda[kc + 1] - pxda[kc]) : 0.f) - p1da[k]) : 0.f;

        float e0 = q0c - q0u;
        float e1 = lok ? (q0c - q0l) : 0.f;
        float e2 = q1c - q1l;
        float e3 = down ? (q1d - q1c) : 0.f;

        float un0 = uo0[k] + SIGMA * e0;
        float un1 = uo1[k] + SIGMA * e1;
        float un2 = uo2[k] + SIGMA * e2;
        float un3 = uo3[k] + SIGMA * e3;

        float s  = un0 * un0 + un1 * un1 + un2 * un2 + un3 * un3;
        float im = fminf(LAM2 * rsqrtf(s), 1.0f);

        nu0[k] = uo0[k] + RHO * (un0 * im - uo0[k]);
        nu1[k] = uo1[k] + RHO * (un1 * im - uo1[k]);
        nu2[k] = uo2[k] + RHO * (un2 * im - uo2[k]);
        nu3[k] = uo3[k] + RHO * (un3 * im - uo3[k]);
    }

    if (last) {
#pragma unroll
        for (int k = 0; k < 4; ++k)
            u2out[idx + k] = make_float4(nu0[k], nu1[k], nu2[k], nu3[k]);
    } else {
        st4(g_u0 + idx, nu0[0], nu0[1], nu0[2], nu0[3]);
        st4(g_u1 + idx, nu1[0], nu1[1], nu1[2], nu1[3]);
        st4(g_u2p + idx, nu2[0], nu2[1], nu2[2], nu2[3]);
        st4(g_u3 + idx, nu3[0], nu3[1], nu3[2], nu3[3]);
    }
}

// ---------------------------------------------------------------------------
// Kernels: 2 adjacent-row quads per thread (rows share halo lines in L1).
// ---------------------------------------------------------------------------
__global__ __launch_bounds__(256) void k_A(float* __restrict__ x2,
                                           float* __restrict__ r2f,
                                           const float* __restrict__ y) {
    int idx = tile_idx2();
#if __CUDA_ARCH__ >= 900
    cudaGridDependencySynchronize();
#endif
    phaseA(idx,     x2, r2f, y);
    phaseA(idx + W, x2, r2f, y);
}

__global__ __launch_bounds__(256) void k_B(float4* __restrict__ u2out, int last) {
    int idx = tile_idx2();
#if __CUDA_ARCH__ >= 900
    cudaGridDependencySynchronize();
#endif
    phaseB(idx,     u2out, last);
    phaseB(idx + W, u2out, last);
}

// ---------------------------------------------------------------------------
// PDL launches.
// ---------------------------------------------------------------------------
template <typename... Args>
static inline void launch_pdl(void (*kern)(Args...), int blocks, int threads,
                              Args... args) {
    cudaLaunchConfig_t cfg = {};
    cfg.gridDim  = dim3(blocks);
    cfg.blockDim = dim3(threads);
    cfg.stream   = 0;
    cudaLaunchAttribute attr[1];
    attr[0].id = cudaLaunchAttributeProgrammaticStreamSerialization;
    attr[0].val.programmaticStreamSerializationAllowed = 1;
    cfg.attrs = attr;
    cfg.numAttrs = 1;
    cudaLaunchKernelEx(&cfg, kern, args...);
}

extern "C" void kernel_launch(void* const* d_in, const int* in_sizes, int n_in,
                              void* d_out, int out_size) {
    const float* y = (const float*)d_in[0];
    float*  out = (float*)d_out;
    float*  x2  = out;
    float*  r2f = out + CHW;
    float4* u2o = (float4*)(out + 3 * CHW);

    const int threads = 256;
    const int blocks  = 384;   // 16 i-tiles x 8 j-tiles x 3 channels

    // setup fuses init + trivial A_0
    k_setup<<<CHW / 4 / threads, threads>>>(y, x2, r2f);
    launch_pdl(k_B, blocks, threads, u2o, 0);          // B_0
    for (int it = 1; it < N_IT; ++it) {
        launch_pdl(k_A, blocks, threads, x2, r2f, (const float*)y);
        launch_pdl(k_B, blocks, threads, u2o, it == N_IT - 1 ? 1 : 0);
    }
}

// round 15
// speedup vs baseline: 3.0088x; 1.0801x over previous
#include <cuda_runtime.h>
#include <cuda_fp16.h>

#define H 512
#define W 512
#define C 3
#define HW (H * W)
#define CHW (C * H * W)
#define N_IT 30

static constexpr float TAU      = (float)0.01;
static constexpr float LAM2     = (float)0.15;
static constexpr float RHO      = (float)1.99;
static constexpr float SIGMA    = (float)(1.0 / 0.01 / 72.0);
static constexpr float TAU_LAM1 = (float)(0.01 * 0.1);
static constexpr float INV_1PT  = (float)(1.0 / 1.01);

// Scratch: fp32 for u planes and px (state / amplified path), fp16 for p0/p1
// (|2r - r2| <= 3e-3 -> fp16 abs rounding ~1.5e-6, negligible through sigma).
__device__ float  g_u0[CHW], g_u1[CHW], g_u2p[CHW], g_u3[CHW];
__device__ float  g_px[CHW];
__device__ __half g_p0[CHW], g_p1[CHW];

__device__ __forceinline__ float4 ld4(const float* p) {
    return *reinterpret_cast<const float4*>(p);
}
__device__ __forceinline__ void st4(float* p, float a, float b, float c, float d) {
    *reinterpret_cast<float4*>(p) = make_float4(a, b, c, d);
}
__device__ __forceinline__ void hld4(const __half* p, float* o) {
    uint2 v = *reinterpret_cast<const uint2*>(p);
    float2 f0 = __half22float2(*reinterpret_cast<const __half2*>(&v.x));
    float2 f1 = __half22float2(*reinterpret_cast<const __half2*>(&v.y));
    o[0] = f0.x; o[1] = f0.y; o[2] = f1.x; o[3] = f1.y;
}
__device__ __forceinline__ float hld1(const __half* p) { return __half2float(*p); }
__device__ __forceinline__ void hst4(__half* p, float a, float b, float c, float d) {
    __half2 h0 = __floats2half2_rn(a, b);
    __half2 h1 = __floats2half2_rn(c, d);
    uint2 v;
    v.x = *reinterpret_cast<unsigned*>(&h0);
    v.y = *reinterpret_cast<unsigned*>(&h1);
    *reinterpret_cast<uint2*>(p) = v;
}

// Tile mapping: block = 32 rows x 64 cols; thread -> 2 row-stacked quads.
__device__ __forceinline__ int tile_idx2() {
    int tid = threadIdx.x;
    int bid = blockIdx.x;
    int c   = bid >> 7;
    int rem = bid & 127;
    int bi  = rem >> 3;
    int bj  = rem & 7;
    int gi  = bi * 32 + (tid >> 4) * 2;
    int gj  = bj * 64 + (tid & 15) * 4;
    return c * HW + gi * W + gj;
}

// ---------------------------------------------------------------------------
// Setup = init + trivial iteration-0 phase A:
//   x2 = y, r2 = 0, u = 0, px = y, p0 = p1 = 0.
// ---------------------------------------------------------------------------
__global__ __launch_bounds__(256) void k_setup(const float* __restrict__ y,
                                               float* __restrict__ x2,
                                               float* __restrict__ r2f) {
    int t = blockIdx.x * blockDim.x + threadIdx.x;
    int idx = t * 4;
    float4 yv = ld4(y + idx);
    *reinterpret_cast<float4*>(x2 + idx)   = yv;
    *reinterpret_cast<float4*>(g_px + idx) = yv;
    st4(r2f + 2 * idx,     0.f, 0.f, 0.f, 0.f);
    st4(r2f + 2 * idx + 4, 0.f, 0.f, 0.f, 0.f);
    hst4(g_p0 + idx, 0.f, 0.f, 0.f, 0.f);
    hst4(g_p1 + idx, 0.f, 0.f, 0.f, 0.f);
    st4(g_u0 + idx, 0.f, 0.f, 0.f, 0.f);
    st4(g_u1 + idx, 0.f, 0.f, 0.f, 0.f);
    st4(g_u2p + idx, 0.f, 0.f, 0.f, 0.f);
    st4(g_u3 + idx, 0.f, 0.f, 0.f, 0.f);
}

// ---------------------------------------------------------------------------
// Phase A body (identical math to R13) for one quad at idx.
// ---------------------------------------------------------------------------
__device__ __forceinline__ void phaseA(int idx, float* __restrict__ x2,
                                       float* __restrict__ r2f,
                                       const float* __restrict__ y) {
    int j0 = idx & (W - 1);
    int i  = (idx >> 9) & (H - 1);
    bool up = (i >= 1), down = (i + 1 < H);
    bool rowlast = (j0 + 4 == W), rowfirst = (j0 == 0);

    const float4 Z = make_float4(0, 0, 0, 0);
    float4 u0cv = ld4(g_u0 + idx);
    float4 u0uv = up   ? ld4(g_u0 + idx - W) : Z;
    float4 u0dv = down ? ld4(g_u0 + idx + W) : Z;
    float4 u1cv = ld4(g_u1 + idx);
    float4 u1uv = up ? ld4(g_u1 + idx - W) : Z;
    float  u1r  = rowlast ? 0.f : g_u1[idx + 4];
    float  u1ur = (up && !rowlast) ? g_u1[idx - W + 4] : 0.f;
    float4 u2cv = ld4(g_u2p + idx);
    float  u2l  = rowfirst ? 0.f : g_u2p[idx - 1];
    float  u2r  = rowlast  ? 0.f : g_u2p[idx + 4];
    float4 u3cv = ld4(g_u3 + idx);
    float4 u3uv = up ? ld4(g_u3 + idx - W) : Z;
    float  u3l  = rowfirst ? 0.f : g_u3[idx - 1];
    float  u3ul = (up && !rowfirst) ? g_u3[idx - W - 1] : 0.f;

    float u0c[4] = {u0cv.x, u0cv.y, u0cv.z, u0cv.w};
    float u0u[4] = {u0uv.x, u0uv.y, u0uv.z, u0uv.w};
    float u0d[4] = {u0dv.x, u0dv.y, u0dv.z, u0dv.w};
    float u1c[5] = {u1cv.x, u1cv.y, u1cv.z, u1cv.w, u1r};
    float u1u[5] = {u1uv.x, u1uv.y, u1uv.z, u1uv.w, u1ur};
    float u2w[6] = {u2l, u2cv.x, u2cv.y, u2cv.z, u2cv.w, u2r};
    float u3w[5] = {u3l, u3cv.x, u3cv.y, u3cv.z, u3cv.w};
    float u3uw[5]= {u3ul, u3uv.x, u3uv.y, u3uv.z, u3uv.w};

    float4 xo4 = ld4(x2 + idx);
    float4 y4  = ld4(y + idx);
    float4 rA  = ld4(r2f + 2 * idx);
    float4 rB  = ld4(r2f + 2 * idx + 4);
    float xoa[4] = {xo4.x, xo4.y, xo4.z, xo4.w};
    float ya[4]  = {y4.x, y4.y, y4.z, y4.w};
    float ro0[4] = {rA.x, rA.z, rB.x, rB.z};
    float ro1[4] = {rA.y, rA.w, rB.y, rB.w};

    float pxo[4], p0o[4], p1o[4], xno[4], rn0[4], rn1[4];
#pragma unroll
    for (int k = 0; k < 4; ++k) {
        bool lok = (k > 0) || !rowfirst;          // j >= 1
        bool rok = (k < 3) || !rowlast;           // j < W-1

        float t0c = TAU * (u0c[k] - (down ? u0d[k] : 0.f)
                           + (lok ? u1c[k] : 0.f) - (rok ? u1c[k + 1] : 0.f));
        float t1c = TAU * (u2w[k + 1] - (rok ? u2w[k + 2] : 0.f)
                           + (up ? u3uw[k + 1] : 0.f) - (down ? u3w[k + 1] : 0.f));
        float t0u = up ? TAU * (u0u[k] - u0c[k]
                                + (lok ? u1u[k] : 0.f) - (rok ? u1u[k + 1] : 0.f))
                       : 0.f;
        float t1l = lok ? TAU * (u2w[k] - u2w[k + 1]
                                 + (up ? u3uw[k] : 0.f) - (down ? u3w[k] : 0.f))
                        : 0.f;

        float dv = t0u - (down ? t0c : 0.f) + t1l - (rok ? t1c : 0.f);
        float x  = (xoa[k] - dv + TAU * ya[k]) * INV_1PT;

        float rr0 = ro0[k] + t0c;
        float rr1 = ro1[k] + t1c;
        float s   = rr0 * rr0 + rr1 * rr1;
        float im  = fminf(TAU_LAM1 * rsqrtf(s), 1.0f);
        float r0  = rr0 - rr0 * im;
        float r1  = rr1 - rr1 * im;

        pxo[k] = 2.0f * x - xoa[k];
        p0o[k] = 2.0f * r0 - ro0[k];
        p1o[k] = 2.0f * r1 - ro1[k];
        xno[k] = xoa[k] + RHO * (x - xoa[k]);
        rn0[k] = ro0[k] + RHO * (r0 - ro0[k]);
        rn1[k] = ro1[k] + RHO * (r1 - ro1[k]);
    }
    st4(g_px + idx, pxo[0], pxo[1], pxo[2], pxo[3]);
    hst4(g_p0 + idx, p0o[0], p0o[1], p0o[2], p0o[3]);
    hst4(g_p1 + idx, p1o[0], p1o[1], p1o[2], p1o[3]);
    st4(x2 + idx, xno[0], xno[1], xno[2], xno[3]);
    st4(r2f + 2 * idx,     rn0[0], rn1[0], rn0[1], rn1[1]);
    st4(r2f + 2 * idx + 4, rn0[2], rn1[2], rn0[3], rn1[3]);
}

// ---------------------------------------------------------------------------
// Phase B body (identical math to R13) for one quad at idx.
// ---------------------------------------------------------------------------
__device__ __forceinline__ void phaseB(int idx, float4* __restrict__ u2out,
                                       int last) {
    int j0 = idx & (W - 1);
    int i  = (idx >> 9) & (H - 1);
    bool up = (i >= 1), down = (i + 1 < H);
    bool rowlast = (j0 + 4 == W), rowfirst = (j0 == 0);

    const float4 Z = make_float4(0, 0, 0, 0);
    float4 pxc = ld4(g_px + idx);
    float4 pxu = up   ? ld4(g_px + idx - W) : Z;
    float4 pxd = down ? ld4(g_px + idx + W) : Z;
    float pxl  = rowfirst ? 0.f : g_px[idx - 1];
    float pxr  = rowlast  ? 0.f : g_px[idx + 4];
    float pxdl = (down && !rowfirst) ? g_px[idx + W - 1] : 0.f;
    float pxdr = (down && !rowlast)  ? g_px[idx + W + 4] : 0.f;

    float p0w[5];
    p0w[0] = rowfirst ? 0.f : hld1(g_p0 + idx - 1);
    hld4(g_p0 + idx, p0w + 1);
    float p0ua[4] = {0, 0, 0, 0};
    if (up) hld4(g_p0 + idx - W, p0ua);
    float p1w[5];
    p1w[0] = rowfirst ? 0.f : hld1(g_p1 + idx - 1);
    hld4(g_p1 + idx, p1w + 1);
    float p1da[4] = {0, 0, 0, 0};
    if (down) hld4(g_p1 + idx + W, p1da);

    float pxa[6]  = {pxl, pxc.x, pxc.y, pxc.z, pxc.w, pxr};
    float pxda[6] = {pxdl, pxd.x, pxd.y, pxd.z, pxd.w, pxdr};
    float pxua[4] = {pxu.x, pxu.y, pxu.z, pxu.w};

    float4 u0c = ld4(g_u0 + idx);
    float4 u1c = ld4(g_u1 + idx);
    float4 u2c = ld4(g_u2p + idx);
    float4 u3c = ld4(g_u3 + idx);
    float uo0[4] = {u0c.x, u0c.y, u0c.z, u0c.w};
    float uo1[4] = {u1c.x, u1c.y, u1c.z, u1c.w};
    float uo2[4] = {u2c.x, u2c.y, u2c.z, u2c.w};
    float uo3[4] = {u3c.x, u3c.y, u3c.z, u3c.w};

    float nu0[4], nu1[4], nu2[4], nu3[4];
#pragma unroll
    for (int k = 0; k < 4; ++k) {
        int kc = k + 1;
        bool lok = (k > 0) || !rowfirst;
        bool rok = (k < 3) || !rowlast;

        float q0c = (down ? (pxda[kc] - pxa[kc]) : 0.f) - p0w[k + 1];
        float q0u = up  ? ((pxa[kc] - pxua[k]) - p0ua[k]) : 0.f;
        float q0l = lok ? ((down ? (pxda[kc - 1] - pxa[kc - 1]) : 0.f) - p0w[k]) : 0.f;
        float q1c = (rok ? (pxa[kc + 1] - pxa[kc]) : 0.f) - p1w[k + 1];
        float q1l = lok ? ((pxa[kc] - pxa[kc - 1]) - p1w[k]) : 0.f;
        float q1d = down ? ((rok ? (pxda[kc + 1] - pxda[kc]) : 0.f) - p1da[k]) : 0.f;

        float e0 = q0c - q0u;
        float e1 = lok ? (q0c - q0l) : 0.f;
        float e2 = q1c - q1l;
        float e3 = down ? (q1d - q1c) : 0.f;

        float un0 = uo0[k] + SIGMA * e0;
        float un1 = uo1[k] + SIGMA * e1;
        float un2 = uo2[k] + SIGMA * e2;
        float un3 = uo3[k] + SIGMA * e3;

        float s  = un0 * un0 + un1 * un1 + un2 * un2 + un3 * un3;
        float im = fminf(LAM2 * rsqrtf(s), 1.0f);

        nu0[k] = uo0[k] + RHO * (un0 * im - uo0[k]);
        nu1[k] = uo1[k] + RHO * (un1 * im - uo1[k]);
        nu2[k] = uo2[k] + RHO * (un2 * im - uo2[k]);
        nu3[k] = uo3[k] + RHO * (un3 * im - uo3[k]);
    }

    if (last) {
#pragma unroll
        for (int k = 0; k < 4; ++k)
            u2out[idx + k] = make_float4(nu0[k], nu1[k], nu2[k], nu3[k]);
    } else {
        st4(g_u0 + idx, nu0[0], nu0[1], nu0[2], nu0[3]);
        st4(g_u1 + idx, nu1[0], nu1[1], nu1[2], nu1[3]);
        st4(g_u2p + idx, nu2[0], nu2[1], nu2[2], nu2[3]);
        st4(g_u3 + idx, nu3[0], nu3[1], nu3[2], nu3[3]);
    }
}

// ---------------------------------------------------------------------------
// Kernels: 2 adjacent-row quads per thread.
// ---------------------------------------------------------------------------
__global__ __launch_bounds__(256) void k_A(float* __restrict__ x2,
                                           float* __restrict__ r2f,
                                           const float* __restrict__ y) {
    int idx = tile_idx2();
#if __CUDA_ARCH__ >= 900
    cudaGridDependencySynchronize();
#endif
    phaseA(idx,     x2, r2f, y);
    phaseA(idx + W, x2, r2f, y);
}

__global__ __launch_bounds__(256) void k_B(float4* __restrict__ u2out, int last) {
    int idx = tile_idx2();
#if __CUDA_ARCH__ >= 900
    cudaGridDependencySynchronize();
#endif
    phaseB(idx,     u2out, last);
    phaseB(idx + W, u2out, last);
}

// ---------------------------------------------------------------------------
// PDL launches.
// ---------------------------------------------------------------------------
template <typename... Args>
static inline void launch_pdl(void (*kern)(Args...), int blocks, int threads,
                              Args... args) {
    cudaLaunchConfig_t cfg = {};
    cfg.gridDim  = dim3(blocks);
    cfg.blockDim = dim3(threads);
    cfg.stream   = 0;
    cudaLaunchAttribute attr[1];
    attr[0].id = cudaLaunchAttributeProgrammaticStreamSerialization;
    attr[0].val.programmaticStreamSerializationAllowed = 1;
    cfg.attrs = attr;
    cfg.numAttrs = 1;
    cudaLaunchKernelEx(&cfg, kern, args...);
}

extern "C" void kernel_launch(void* const* d_in, const int* in_sizes, int n_in,
                              void* d_out, int out_size) {
    const float* y = (const float*)d_in[0];
    float*  out = (float*)d_out;
    float*  x2  = out;
    float*  r2f = out + CHW;
    float4* u2o = (float4*)(out + 3 * CHW);

    const int threads = 256;
    const int blocks  = 384;   // 16 i-tiles x 8 j-tiles x 3 channels

    k_setup<<<CHW / 4 / threads, threads>>>(y, x2, r2f);
    launch_pdl(k_B, blocks, threads, u2o, 0);          // B_0
    for (int it = 1; it < N_IT; ++it) {
        launch_pdl(k_A, blocks, threads, x2, r2f, (const float*)y);
        launch_pdl(k_B, blocks, threads, u2o, it == N_IT - 1 ? 1 : 0);
    }
}